// round 5
// baseline (speedup 1.0000x reference)
#include <cuda_runtime.h>
#include <cstdint>
#include <cstddef>

// ---------------- dims ----------------
#define BB   2
#define NN   256
#define DN   128
#define DE   64
#define DH   128
#define HH   8
#define DHH  16
#define DNH  512
#define DEH  256
#define LL   2

#define SCALE 0.08838834764831845f   // 1/sqrt(128)

// ---------------- persistent scratch (no allocs allowed) ----------------
__device__ float g_x[BB*NN*DN];                     // 65536
__device__ float g_qkvn[BB*NN*3*DH];                // 196608
__device__ float g_dots[BB*NN*HH*NN];               // 1M  layout (b,i,h,j)
__device__ float g_v[(size_t)BB*NN*NN*DH];          // 16.7M layout (b,i,j,hd)
__device__ float g_s[BB*NN*DEH];                    // src proj
__device__ float g_t[BB*NN*DEH];                    // tgt proj
__device__ float g_ebuf1[(size_t)BB*NN*NN*DE];      // layer0 edge out
__device__ float g_ebuf0[(size_t)BB*NN*NN*DE];      // layer1 edge out (final)

__device__ __forceinline__ float gelu_f(float x) {
    return 0.5f * x * (1.0f + erff(x * 0.70710678118654752440f));
}

// ---------------- k_copy_x : node_features -> g_x ----------------
__global__ void k_copy_x(const float* __restrict__ node) {
    int i = blockIdx.x * blockDim.x + threadIdx.x;
    if (i < BB*NN*DN) g_x[i] = node[i];
}

// ---------------- k_qkvn : qkv_n = x @ Wqkv_n[l] ----------------
// grid = 512 rows, 128 threads
__global__ void k_qkvn(const float* __restrict__ W) {
    __shared__ float xs[DN];
    int row = blockIdx.x, tid = threadIdx.x;
    xs[tid] = g_x[row*DN + tid];
    __syncthreads();
    float a0 = 0.f, a1 = 0.f, a2 = 0.f;
#pragma unroll 8
    for (int k = 0; k < DN; k++) {
        float xv = xs[k];
        const float* w = W + k*384;
        a0 += xv * w[tid];
        a1 += xv * w[tid + 128];
        a2 += xv * w[tid + 256];
    }
    float* o = g_qkvn + row*384;
    o[tid] = a0; o[tid + 128] = a1; o[tid + 256] = a2;
}

// ---------------- k_attn1 : per-pair qkv_e GEMM -> dots, v ----------------
// grid = 512 (b*N+i), 256 threads, dynamic smem
#define ATTN1_SMEM_F (32768 + 16384 + 128 + 2048)
__global__ void __launch_bounds__(256, 1)
k_attn1(const float* __restrict__ e_in, const float* __restrict__ W) {
    extern __shared__ float sm[];
    float* Ws  = sm;                 // 64 x 512
    float* Es  = Ws + 32768;         // 256 x 64 (e row)
    float* QNs = Es + 16384;         // 128 (q of node i, h-major)
    float* QKVs = QNs + 128;         // 4 x 512 staging

    int bi = blockIdx.x;
    int b = bi >> 8;
    int tid = threadIdx.x;

    {   // load weights + e row (float4)
        const float4* Wg = (const float4*)W;
        float4* Ws4 = (float4*)Ws;
        for (int idx = tid; idx < 8192; idx += 256) Ws4[idx] = Wg[idx];
        const float4* Eg = (const float4*)(e_in + (size_t)bi * (NN*DE));
        float4* Es4 = (float4*)Es;
        for (int idx = tid; idx < 4096; idx += 256) Es4[idx] = Eg[idx];
    }
    if (tid < 128) {
        int h = tid >> 4, d = tid & 15;
        QNs[tid] = g_qkvn[bi*384 + h*48 + d];
    }
    __syncthreads();

    const float2* W2 = (const float2*)Ws;      // [64][256] of float2
    float2* Q2 = (float2*)QKVs;

    for (int j0 = 0; j0 < NN; j0 += 4) {
        float2 a0 = {0.f,0.f}, a1 = {0.f,0.f}, a2 = {0.f,0.f}, a3 = {0.f,0.f};
        const float* ep = Es + j0*64;
#pragma unroll 8
        for (int k = 0; k < 64; k++) {
            float2 w = W2[k*256 + tid];
            float e0 = ep[k], e1 = ep[64 + k], e2 = ep[128 + k], e3 = ep[192 + k];
            a0.x += e0*w.x; a0.y += e0*w.y;
            a1.x += e1*w.x; a1.y += e1*w.y;
            a2.x += e2*w.x; a2.y += e2*w.y;
            a3.x += e3*w.x; a3.y += e3*w.y;
        }
        Q2[0*256 + tid] = a0;
        Q2[1*256 + tid] = a1;
        Q2[2*256 + tid] = a2;
        Q2[3*256 + tid] = a3;
        __syncthreads();

        if (tid < 128) {
            int h = tid >> 4, d = tid & 15;
            float qn = QNs[tid];
#pragma unroll
            for (int jj = 0; jj < 4; jj++) {
                int j = j0 + jj;
                const float* qv = QKVs + jj*512 + h*64;
                float eq = qv[d], ek = qv[16 + d], ev = qv[32 + d], em = qv[48 + d];
                const float* kv = g_qkvn + (b*NN + j)*384 + h*48;
                float kn = kv[16 + d], vn = kv[32 + d];
                float pd = (qn + eq) * (kn + ek);
                pd += __shfl_xor_sync(0xffffffffu, pd, 8);
                pd += __shfl_xor_sync(0xffffffffu, pd, 4);
                pd += __shfl_xor_sync(0xffffffffu, pd, 2);
                pd += __shfl_xor_sync(0xffffffffu, pd, 1);
                if (d == 0) g_dots[(bi*HH + h)*NN + j] = pd * SCALE;
                g_v[((size_t)bi*NN + j)*DH + tid] = vn * em + ev;
            }
        }
        __syncthreads();
    }
}

// ---------------- k_attn2 : softmax + AV + Wo + Wl0 + LN + node MLP + LN ----------------
// grid = 512, 128 threads
__global__ void __launch_bounds__(128)
k_attn2(const float* __restrict__ Wo, const float* __restrict__ bo,
        const float* __restrict__ Wl0, const float* __restrict__ bl0,
        const float* __restrict__ g0, const float* __restrict__ b0,
        const float* __restrict__ Wm1, const float* __restrict__ Wm2,
        const float* __restrict__ bm2,
        const float* __restrict__ g1, const float* __restrict__ b1) {
    __shared__ float ds[HH*NN];     // 2048: dots -> probs
    __shared__ float outs[DH];
    __shared__ float hid[DNH];
    __shared__ float red[8];
    __shared__ float invs[HH];
    __shared__ float asm_[DH];
    __shared__ float xs[DN];

    int bi = blockIdx.x, tid = threadIdx.x;
    const float* drow = g_dots + bi*(HH*NN);
    for (int idx = tid; idx < HH*NN; idx += 128) ds[idx] = drow[idx];
    __syncthreads();

    int h = tid >> 4, d = tid & 15;
    {   // softmax per head (16 lanes per head)
        float m = -1e30f;
#pragma unroll
        for (int k = 0; k < 16; k++) m = fmaxf(m, ds[h*NN + k*16 + d]);
        for (int o = 8; o; o >>= 1) m = fmaxf(m, __shfl_xor_sync(0xffffffffu, m, o));
        float s = 0.f;
#pragma unroll
        for (int k = 0; k < 16; k++) {
            float p = __expf(ds[h*NN + k*16 + d] - m);
            ds[h*NN + k*16 + d] = p;
            s += p;
        }
        for (int o = 8; o; o >>= 1) s += __shfl_xor_sync(0xffffffffu, s, o);
        if (d == 0) invs[h] = 1.0f / s;
    }
    __syncthreads();

    {   // out[h,d] = sum_j p * v
        float acc = 0.f;
        const float* vrow = g_v + (size_t)bi * (NN*DH);
        const float* pr = ds + h*NN;
#pragma unroll 4
        for (int j = 0; j < NN; j++) acc += pr[j] * vrow[j*DH + tid];
        outs[tid] = acc * invs[h];
    }
    __syncthreads();

    // attn_out = outs @ Wo + bo
    float ao = bo[tid];
#pragma unroll 4
    for (int k = 0; k < DH; k++) ao += outs[k] * Wo[k*DN + tid];
    asm_[tid] = ao;
    __syncthreads();

    // y = attn_out @ Wl0 + bl0 ; x1 = LN(x + y)
    float y = bl0[tid];
#pragma unroll 4
    for (int k = 0; k < DN; k++) y += asm_[k] * Wl0[k*DN + tid];
    float xv = g_x[bi*DN + tid] + y;

    float s1 = xv, s2 = xv*xv;
    for (int o = 16; o; o >>= 1) { s1 += __shfl_xor_sync(0xffffffffu, s1, o); s2 += __shfl_xor_sync(0xffffffffu, s2, o); }
    int w = tid >> 5;
    if ((tid & 31) == 0) { red[w*2] = s1; red[w*2+1] = s2; }
    __syncthreads();
    s1 = red[0]+red[2]+red[4]+red[6];
    s2 = red[1]+red[3]+red[5]+red[7];
    float mean = s1 * (1.0f/DN);
    float var  = s2 * (1.0f/DN) - mean*mean;
    float x1 = (xv - mean) * rsqrtf(var + 1e-5f) * g0[tid] + b0[tid];
    xs[tid] = x1;
    __syncthreads();

    // MLP: hid = gelu(x1 @ Wm1); 4 cols/thread via float4
    {
        float4 hv = {0.f,0.f,0.f,0.f};
        const float4* W1 = (const float4*)Wm1;
#pragma unroll 4
        for (int k = 0; k < DN; k++) {
            float xk = xs[k];
            float4 wv = W1[k*(DNH/4) + tid];
            hv.x += xk*wv.x; hv.y += xk*wv.y; hv.z += xk*wv.z; hv.w += xk*wv.w;
        }
        hid[4*tid+0] = gelu_f(hv.x);
        hid[4*tid+1] = gelu_f(hv.y);
        hid[4*tid+2] = gelu_f(hv.z);
        hid[4*tid+3] = gelu_f(hv.w);
    }
    __syncthreads();

    float o2 = bm2[tid];
#pragma unroll 4
    for (int k = 0; k < DNH; k++) o2 += hid[k] * Wm2[k*DN + tid];
    float x2 = x1 + o2;

    s1 = x2; s2 = x2*x2;
    for (int o = 16; o; o >>= 1) { s1 += __shfl_xor_sync(0xffffffffu, s1, o); s2 += __shfl_xor_sync(0xffffffffu, s2, o); }
    __syncthreads();   // red reuse
    if ((tid & 31) == 0) { red[w*2] = s1; red[w*2+1] = s2; }
    __syncthreads();
    s1 = red[0]+red[2]+red[4]+red[6];
    s2 = red[1]+red[3]+red[5]+red[7];
    mean = s1 * (1.0f/DN);
    var  = s2 * (1.0f/DN) - mean*mean;
    g_x[bi*DN + tid] = (x2 - mean) * rsqrtf(var + 1e-5f) * g1[tid] + b1[tid];
}

// ---------------- k_srctgt : s = x@Ws+bs, t = x@Wt+bt ----------------
// grid = 512, 256 threads
__global__ void __launch_bounds__(256)
k_srctgt(const float* __restrict__ Wsm, const float* __restrict__ bsv,
         const float* __restrict__ Wtm, const float* __restrict__ btv) {
    __shared__ float xs[DN];
    int row = blockIdx.x, tid = threadIdx.x;
    if (tid < DN) xs[tid] = g_x[row*DN + tid];
    __syncthreads();
    float s = bsv[tid], t = btv[tid];
#pragma unroll 4
    for (int k = 0; k < DN; k++) {
        float xv = xs[k];
        s += xv * Wsm[k*DEH + tid];
        t += xv * Wtm[k*DEH + tid];
    }
    g_s[row*DEH + tid] = s;
    g_t[row*DEH + tid] = t;
}

// ---------------- k_e1 : h = gelu(ecat@We0+be0+src+tgt); e' = LN(e + h@We1+be1) ----------------
// grid = 512 (b,i), 256 threads, dynamic smem
#define E1_SMEM_F (32768 + 16384 + 256 + 512 + 1024 + 16)
__global__ void __launch_bounds__(256, 1)
k_e1(const float* __restrict__ e_in, float* __restrict__ e_out,
     const float* __restrict__ We0, const float* __restrict__ be0,
     const float* __restrict__ We1, const float* __restrict__ be1,
     const float* __restrict__ g0, const float* __restrict__ b0) {
    extern __shared__ float sm[];
    float* W0s  = sm;             // 128 x 256
    float* W1s  = W0s + 32768;    // 256 x 64
    float* srcs = W1s + 16384;    // 256
    float* ecat = srcs + 256;     // 4 x 128
    float* hid  = ecat + 512;     // 4 x 256
    float* redS = hid + 1024;     // 8
    float* redQ = redS + 8;       // 8

    int bi = blockIdx.x;
    int b = bi >> 8, i = bi & 255;
    int tid = threadIdx.x;

    {
        const float4* Wg0 = (const float4*)We0;
        float4* d0 = (float4*)W0s;
        for (int idx = tid; idx < 8192; idx += 256) d0[idx] = Wg0[idx];
        const float4* Wg1 = (const float4*)We1;
        float4* d1 = (float4*)W1s;
        for (int idx = tid; idx < 4096; idx += 256) d1[idx] = Wg1[idx];
    }
    srcs[tid] = g_s[bi*DEH + tid] + be0[tid];
    __syncthreads();

    int jj2 = tid >> 6, c2 = tid & 63;   // phase2 mapping
    int wmy = tid >> 5;

    for (int j0 = 0; j0 < NN; j0 += 4) {
        // stage ecat = [e_ij, e_ji] for 4 pairs
#pragma unroll
        for (int it = 0; it < 2; it++) {
            int idx = tid + it*256;
            int jj = idx >> 7, c = idx & 127;
            int j = j0 + jj;
            float v;
            if (c < 64) v = e_in[((size_t)bi*NN + j)*DE + c];
            else        v = e_in[(((size_t)b*NN + j)*NN + i)*DE + (c - 64)];
            ecat[idx] = v;
        }
        __syncthreads();

        // phase1: hidden col c = tid for 4 pairs
        float a0 = srcs[tid] + g_t[((size_t)b*NN + (j0+0))*DEH + tid];
        float a1 = srcs[tid] + g_t[((size_t)b*NN + (j0+1))*DEH + tid];
        float a2 = srcs[tid] + g_t[((size_t)b*NN + (j0+2))*DEH + tid];
        float a3 = srcs[tid] + g_t[((size_t)b*NN + (j0+3))*DEH + tid];
#pragma unroll 8
        for (int k = 0; k < 128; k++) {
            float w = W0s[k*256 + tid];
            a0 += ecat[k]       * w;
            a1 += ecat[128 + k] * w;
            a2 += ecat[256 + k] * w;
            a3 += ecat[384 + k] * w;
        }
        hid[tid]       = gelu_f(a0);
        hid[256 + tid] = gelu_f(a1);
        hid[512 + tid] = gelu_f(a2);
        hid[768 + tid] = gelu_f(a3);
        __syncthreads();

        // phase2: out col c (64) for pair jj
        int j = j0 + jj2;
        float o = be1[c2];
        const float* hp = hid + jj2*256;
#pragma unroll 8
        for (int k = 0; k < 256; k++) o += hp[k] * W1s[k*64 + c2];
        float r = ecat[jj2*128 + c2] + o;

        float s1 = r, s2 = r*r;
        for (int off = 16; off; off >>= 1) {
            s1 += __shfl_xor_sync(0xffffffffu, s1, off);
            s2 += __shfl_xor_sync(0xffffffffu, s2, off);
        }
        if ((tid & 31) == 0) { redS[wmy] = s1; redQ[wmy] = s2; }
        __syncthreads();
        float sum = redS[2*jj2] + redS[2*jj2+1];
        float sq  = redQ[2*jj2] + redQ[2*jj2+1];
        float mean = sum * (1.0f/DE);
        float var  = sq  * (1.0f/DE) - mean*mean;
        e_out[((size_t)bi*NN + j)*DE + c2] =
            (r - mean) * rsqrtf(var + 1e-5f) * g0[c2] + b0[c2];
        __syncthreads();
    }
}

// ---------------- k_e2 : e = LN(e + gelu(e@Wem1)@Wem2 + bem2) in place ----------------
// grid = 512, 256 threads, dynamic smem
#define E2_SMEM_F (16384 + 16384 + 256 + 1024 + 16)
__global__ void __launch_bounds__(256, 1)
k_e2(float* __restrict__ e_io,
     const float* __restrict__ Wem1, const float* __restrict__ Wem2,
     const float* __restrict__ bem2,
     const float* __restrict__ g1, const float* __restrict__ b1) {
    extern __shared__ float sm[];
    float* W1s = sm;            // 64 x 256
    float* W2s = W1s + 16384;   // 256 x 64
    float* es  = W2s + 16384;   // 4 x 64
    float* hid = es + 256;      // 4 x 256
    float* redS = hid + 1024;   // 8
    float* redQ = redS + 8;     // 8

    int bi = blockIdx.x, tid = threadIdx.x;
    {
        const float4* Wg1 = (const float4*)Wem1;
        float4* d1 = (float4*)W1s;
        for (int idx = tid; idx < 4096; idx += 256) d1[idx] = Wg1[idx];
        const float4* Wg2 = (const float4*)Wem2;
        float4* d2 = (float4*)W2s;
        for (int idx = tid; idx < 4096; idx += 256) d2[idx] = Wg2[idx];
    }
    __syncthreads();

    int jj2 = tid >> 6, c2 = tid & 63;
    int wmy = tid >> 5;

    for (int j0 = 0; j0 < NN; j0 += 4) {
        es[tid] = e_io[((size_t)bi*NN + (j0 + jj2))*DE + c2];
        __syncthreads();

        float a0 = 0.f, a1 = 0.f, a2 = 0.f, a3 = 0.f;
#pragma unroll 8
        for (int k = 0; k < 64; k++) {
            float w = W1s[k*256 + tid];
            a0 += es[k]       * w;
            a1 += es[64 + k]  * w;
            a2 += es[128 + k] * w;
            a3 += es[192 + k] * w;
        }
        hid[tid]       = gelu_f(a0);
        hid[256 + tid] = gelu_f(a1);
        hid[512 + tid] = gelu_f(a2);
        hid[768 + tid] = gelu_f(a3);
        __syncthreads();

        float o = bem2[c2];
        const float* hp = hid + jj2*256;
#pragma unroll 8
        for (int k = 0; k < 256; k++) o += hp[k] * W2s[k*64 + c2];
        float r = es[tid] + o;

        float s1 = r, s2 = r*r;
        for (int off = 16; off; off >>= 1) {
            s1 += __shfl_xor_sync(0xffffffffu, s1, off);
            s2 += __shfl_xor_sync(0xffffffffu, s2, off);
        }
        if ((tid & 31) == 0) { redS[wmy] = s1; redQ[wmy] = s2; }
        __syncthreads();
        float sum = redS[2*jj2] + redS[2*jj2+1];
        float sq  = redQ[2*jj2] + redQ[2*jj2+1];
        float mean = sum * (1.0f/DE);
        float var  = sq  * (1.0f/DE) - mean*mean;
        e_io[((size_t)bi*NN + (j0 + jj2))*DE + c2] =
            (r - mean) * rsqrtf(var + 1e-5f) * g1[c2] + b1[c2];
        __syncthreads();
    }
}

// ---------------- k_final : pack (x, e) into d_out ----------------
__global__ void k_final(float* __restrict__ out) {
    int idx = blockIdx.x * blockDim.x + threadIdx.x;
    const int nx = BB*NN*DN;
    const int ne = BB*NN*NN*DE;
    if (idx < nx) out[idx] = g_x[idx];
    else if (idx < nx + ne) out[idx] = g_ebuf0[idx - nx];
}

// ---------------- launch ----------------
extern "C" void kernel_launch(void* const* d_in, const int* in_sizes, int n_in,
                              void* d_out, int out_size) {
    const float* node    = (const float*)d_in[0];
    const float* edge    = (const float*)d_in[1];
    const float* Wqkv_n  = (const float*)d_in[2];
    const float* Wqkv_e  = (const float*)d_in[3];
    const float* Wo      = (const float*)d_in[4];
    const float* bo      = (const float*)d_in[5];
    const float* Wl0     = (const float*)d_in[6];
    const float* bl0     = (const float*)d_in[7];
    const float* ln0_g   = (const float*)d_in[8];
    const float* ln0_b   = (const float*)d_in[9];
    const float* Wm1     = (const float*)d_in[10];
    const float* Wm2     = (const float*)d_in[11];
    const float* bm2     = (const float*)d_in[12];
    const float* ln1_g   = (const float*)d_in[13];
    const float* ln1_b   = (const float*)d_in[14];
    const float* We0     = (const float*)d_in[15];
    const float* be0     = (const float*)d_in[16];
    const float* Wsm     = (const float*)d_in[17];
    const float* bsv     = (const float*)d_in[18];
    const float* Wtm     = (const float*)d_in[19];
    const float* btv     = (const float*)d_in[20];
    const float* We1     = (const float*)d_in[21];
    const float* be1     = (const float*)d_in[22];
    const float* eln0_g  = (const float*)d_in[23];
    const float* eln0_b  = (const float*)d_in[24];
    const float* Wem1    = (const float*)d_in[25];
    const float* Wem2    = (const float*)d_in[26];
    const float* bem2    = (const float*)d_in[27];
    const float* eln1_g  = (const float*)d_in[28];
    const float* eln1_b  = (const float*)d_in[29];
    float* out = (float*)d_out;

    cudaFuncSetAttribute(k_attn1, cudaFuncAttributeMaxDynamicSharedMemorySize, ATTN1_SMEM_F*4);
    cudaFuncSetAttribute(k_e1,    cudaFuncAttributeMaxDynamicSharedMemorySize, E1_SMEM_F*4);
    cudaFuncSetAttribute(k_e2,    cudaFuncAttributeMaxDynamicSharedMemorySize, E2_SMEM_F*4);

    float *pe0, *pe1;
    cudaGetSymbolAddress((void**)&pe0, g_ebuf0);
    cudaGetSymbolAddress((void**)&pe1, g_ebuf1);

    k_copy_x<<<(BB*NN*DN + 255)/256, 256>>>(node);

    const float* e_in = edge;   // layer 0 reads original edge features
    float* e_out = pe1;

    for (int l = 0; l < LL; l++) {
        k_qkvn<<<BB*NN, 128>>>(Wqkv_n + (size_t)l*DN*3*DH);
        k_attn1<<<BB*NN, 256, ATTN1_SMEM_F*4>>>(e_in, Wqkv_e + (size_t)l*DE*4*DH);
        k_attn2<<<BB*NN, 128>>>(Wo + (size_t)l*DH*DN, bo + (size_t)l*DN,
                                Wl0 + (size_t)l*DN*DN, bl0 + (size_t)l*DN,
                                ln0_g + (size_t)l*DN, ln0_b + (size_t)l*DN,
                                Wm1 + (size_t)l*DN*DNH, Wm2 + (size_t)l*DNH*DN,
                                bm2 + (size_t)l*DN,
                                ln1_g + (size_t)l*DN, ln1_b + (size_t)l*DN);
        k_srctgt<<<BB*NN, 256>>>(Wsm + (size_t)l*DN*DEH, bsv + (size_t)l*DEH,
                                 Wtm + (size_t)l*DN*DEH, btv + (size_t)l*DEH);
        k_e1<<<BB*NN, 256, E1_SMEM_F*4>>>(e_in, e_out,
                                          We0 + (size_t)l*2*DE*DEH, be0 + (size_t)l*DEH,
                                          We1 + (size_t)l*DEH*DE, be1 + (size_t)l*DE,
                                          eln0_g + (size_t)l*DE, eln0_b + (size_t)l*DE);
        k_e2<<<BB*NN, 256, E2_SMEM_F*4>>>(e_out,
                                          Wem1 + (size_t)l*DE*DEH, Wem2 + (size_t)l*DEH*DE,
                                          bem2 + (size_t)l*DE,
                                          eln1_g + (size_t)l*DE, eln1_b + (size_t)l*DE);
        e_in = e_out;
        e_out = pe0;   // layer 1 writes the final buffer
    }

    int total = BB*NN*DN + BB*NN*NN*DE;
    k_final<<<(total + 255)/256, 256>>>(out);
}

// round 8
// speedup vs baseline: 1.0010x; 1.0010x over previous
#include <cuda_runtime.h>
#include <cstdint>
#include <cstddef>

// ---------------- dims ----------------
#define BB   2
#define NN   256
#define DN   128
#define DE   64
#define DH   128
#define HH   8
#define DHH  16
#define DNH  512
#define DEH  256
#define LL   2

#define SCALE 0.08838834764831845f   // 1/sqrt(128)

// ---------------- persistent scratch (no allocs allowed) ----------------
__device__ float g_x[BB*NN*DN];                     // 65536
__device__ float g_qkvn[BB*NN*3*DH];                // 196608
__device__ float g_dots[BB*NN*HH*NN];               // 1M  layout (b,i,h,j)
__device__ float g_v[(size_t)BB*NN*NN*DH];          // 16.7M layout (b,i,j,hd)
__device__ float g_s[BB*NN*DEH];                    // src proj
__device__ float g_t[BB*NN*DEH];                    // tgt proj
__device__ float g_ebuf1[(size_t)BB*NN*NN*DE];      // layer0 edge out
__device__ float g_ebuf0[(size_t)BB*NN*NN*DE];      // layer1 edge out (final)

__device__ __forceinline__ float gelu_f(float x) {
    return 0.5f * x * (1.0f + erff(x * 0.70710678118654752440f));
}

// ---------------- k_copy_x : node_features -> g_x ----------------
__global__ void k_copy_x(const float* __restrict__ node) {
    int i = blockIdx.x * blockDim.x + threadIdx.x;
    if (i < BB*NN*DN) g_x[i] = node[i];
}

// ---------------- k_qkvn : qkv_n = x @ Wqkv_n[l] ----------------
// grid = 512 rows, 128 threads
__global__ void k_qkvn(const float* __restrict__ W) {
    __shared__ float xs[DN];
    int row = blockIdx.x, tid = threadIdx.x;
    xs[tid] = g_x[row*DN + tid];
    __syncthreads();
    float a0 = 0.f, a1 = 0.f, a2 = 0.f;
#pragma unroll 8
    for (int k = 0; k < DN; k++) {
        float xv = xs[k];
        const float* w = W + k*384;
        a0 += xv * w[tid];
        a1 += xv * w[tid + 128];
        a2 += xv * w[tid + 256];
    }
    float* o = g_qkvn + row*384;
    o[tid] = a0; o[tid + 128] = a1; o[tid + 256] = a2;
}

// ---------------- k_attn1 : per-pair qkv_e GEMM -> dots, v ----------------
// grid = 512 (b*N+i), 256 threads, dynamic smem
#define ATTN1_SMEM_F (32768 + 16384 + 128 + 2048)
__global__ void __launch_bounds__(256, 1)
k_attn1(const float* __restrict__ e_in, const float* __restrict__ W) {
    extern __shared__ float sm[];
    float* Ws  = sm;                 // 64 x 512
    float* Es  = Ws + 32768;         // 256 x 64 (e row)
    float* QNs = Es + 16384;         // 128 (q of node i, h-major)
    float* QKVs = QNs + 128;         // 4 x 512 staging

    int bi = blockIdx.x;
    int b = bi >> 8;
    int tid = threadIdx.x;

    {   // load weights + e row (float4)
        const float4* Wg = (const float4*)W;
        float4* Ws4 = (float4*)Ws;
        for (int idx = tid; idx < 8192; idx += 256) Ws4[idx] = Wg[idx];
        const float4* Eg = (const float4*)(e_in + (size_t)bi * (NN*DE));
        float4* Es4 = (float4*)Es;
        for (int idx = tid; idx < 4096; idx += 256) Es4[idx] = Eg[idx];
    }
    if (tid < 128) {
        int h = tid >> 4, d = tid & 15;
        QNs[tid] = g_qkvn[bi*384 + h*48 + d];
    }
    __syncthreads();

    const float2* W2 = (const float2*)Ws;      // [64][256] of float2
    float2* Q2 = (float2*)QKVs;

    for (int j0 = 0; j0 < NN; j0 += 4) {
        float2 a0 = {0.f,0.f}, a1 = {0.f,0.f}, a2 = {0.f,0.f}, a3 = {0.f,0.f};
        const float* ep = Es + j0*64;
#pragma unroll 8
        for (int k = 0; k < 64; k++) {
            float2 w = W2[k*256 + tid];
            float e0 = ep[k], e1 = ep[64 + k], e2 = ep[128 + k], e3 = ep[192 + k];
            a0.x += e0*w.x; a0.y += e0*w.y;
            a1.x += e1*w.x; a1.y += e1*w.y;
            a2.x += e2*w.x; a2.y += e2*w.y;
            a3.x += e3*w.x; a3.y += e3*w.y;
        }
        Q2[0*256 + tid] = a0;
        Q2[1*256 + tid] = a1;
        Q2[2*256 + tid] = a2;
        Q2[3*256 + tid] = a3;
        __syncthreads();

        if (tid < 128) {
            int h = tid >> 4, d = tid & 15;
            float qn = QNs[tid];
#pragma unroll
            for (int jj = 0; jj < 4; jj++) {
                int j = j0 + jj;
                const float* qv = QKVs + jj*512 + h*64;
                float eq = qv[d], ek = qv[16 + d], ev = qv[32 + d], em = qv[48 + d];
                const float* kv = g_qkvn + (b*NN + j)*384 + h*48;
                float kn = kv[16 + d], vn = kv[32 + d];
                float pd = (qn + eq) * (kn + ek);
                pd += __shfl_xor_sync(0xffffffffu, pd, 8);
                pd += __shfl_xor_sync(0xffffffffu, pd, 4);
                pd += __shfl_xor_sync(0xffffffffu, pd, 2);
                pd += __shfl_xor_sync(0xffffffffu, pd, 1);
                if (d == 0) g_dots[(bi*HH + h)*NN + j] = pd * SCALE;
                g_v[((size_t)bi*NN + j)*DH + tid] = vn * em + ev;
            }
        }
        __syncthreads();
    }
}

// ---------------- k_attn2 : softmax + AV + Wo + Wl0 + LN + node MLP + LN ----------------
// grid = 512, 128 threads
__global__ void __launch_bounds__(128)
k_attn2(const float* __restrict__ Wo, const float* __restrict__ bo,
        const float* __restrict__ Wl0, const float* __restrict__ bl0,
        const float* __restrict__ g0, const float* __restrict__ b0,
        const float* __restrict__ Wm1, const float* __restrict__ Wm2,
        const float* __restrict__ bm2,
        const float* __restrict__ g1, const float* __restrict__ b1) {
    __shared__ float ds[HH*NN];     // 2048: dots -> probs
    __shared__ float outs[DH];
    __shared__ float hid[DNH];
    __shared__ float red[8];
    __shared__ float invs[HH];
    __shared__ float asm_[DH];
    __shared__ float xs[DN];

    int bi = blockIdx.x, tid = threadIdx.x;
    const float* drow = g_dots + bi*(HH*NN);
    for (int idx = tid; idx < HH*NN; idx += 128) ds[idx] = drow[idx];
    __syncthreads();

    int h = tid >> 4, d = tid & 15;
    {   // softmax per head (16 lanes per head)
        float m = -1e30f;
#pragma unroll
        for (int k = 0; k < 16; k++) m = fmaxf(m, ds[h*NN + k*16 + d]);
        for (int o = 8; o; o >>= 1) m = fmaxf(m, __shfl_xor_sync(0xffffffffu, m, o));
        float s = 0.f;
#pragma unroll
        for (int k = 0; k < 16; k++) {
            float p = __expf(ds[h*NN + k*16 + d] - m);
            ds[h*NN + k*16 + d] = p;
            s += p;
        }
        for (int o = 8; o; o >>= 1) s += __shfl_xor_sync(0xffffffffu, s, o);
        if (d == 0) invs[h] = 1.0f / s;
    }
    __syncthreads();

    {   // out[h,d] = sum_j p * v
        float acc = 0.f;
        const float* vrow = g_v + (size_t)bi * (NN*DH);
        const float* pr = ds + h*NN;
#pragma unroll 4
        for (int j = 0; j < NN; j++) acc += pr[j] * vrow[j*DH + tid];
        outs[tid] = acc * invs[h];
    }
    __syncthreads();

    // attn_out = outs @ Wo + bo
    float ao = bo[tid];
#pragma unroll 4
    for (int k = 0; k < DH; k++) ao += outs[k] * Wo[k*DN + tid];
    asm_[tid] = ao;
    __syncthreads();

    // y = attn_out @ Wl0 + bl0 ; x1 = LN(x + y)
    float y = bl0[tid];
#pragma unroll 4
    for (int k = 0; k < DN; k++) y += asm_[k] * Wl0[k*DN + tid];
    float xv = g_x[bi*DN + tid] + y;

    float s1 = xv, s2 = xv*xv;
    for (int o = 16; o; o >>= 1) { s1 += __shfl_xor_sync(0xffffffffu, s1, o); s2 += __shfl_xor_sync(0xffffffffu, s2, o); }
    int w = tid >> 5;
    if ((tid & 31) == 0) { red[w*2] = s1; red[w*2+1] = s2; }
    __syncthreads();
    s1 = red[0]+red[2]+red[4]+red[6];
    s2 = red[1]+red[3]+red[5]+red[7];
    float mean = s1 * (1.0f/DN);
    float var  = s2 * (1.0f/DN) - mean*mean;
    float x1 = (xv - mean) * rsqrtf(var + 1e-5f) * g0[tid] + b0[tid];
    xs[tid] = x1;
    __syncthreads();

    // MLP: hid = gelu(x1 @ Wm1); 4 cols/thread via float4
    {
        float4 hv = {0.f,0.f,0.f,0.f};
        const float4* W1 = (const float4*)Wm1;
#pragma unroll 4
        for (int k = 0; k < DN; k++) {
            float xk = xs[k];
            float4 wv = W1[k*(DNH/4) + tid];
            hv.x += xk*wv.x; hv.y += xk*wv.y; hv.z += xk*wv.z; hv.w += xk*wv.w;
        }
        hid[4*tid+0] = gelu_f(hv.x);
        hid[4*tid+1] = gelu_f(hv.y);
        hid[4*tid+2] = gelu_f(hv.z);
        hid[4*tid+3] = gelu_f(hv.w);
    }
    __syncthreads();

    float o2 = bm2[tid];
#pragma unroll 4
    for (int k = 0; k < DNH; k++) o2 += hid[k] * Wm2[k*DN + tid];
    float x2 = x1 + o2;

    s1 = x2; s2 = x2*x2;
    for (int o = 16; o; o >>= 1) { s1 += __shfl_xor_sync(0xffffffffu, s1, o); s2 += __shfl_xor_sync(0xffffffffu, s2, o); }
    __syncthreads();   // red reuse
    if ((tid & 31) == 0) { red[w*2] = s1; red[w*2+1] = s2; }
    __syncthreads();
    s1 = red[0]+red[2]+red[4]+red[6];
    s2 = red[1]+red[3]+red[5]+red[7];
    mean = s1 * (1.0f/DN);
    var  = s2 * (1.0f/DN) - mean*mean;
    g_x[bi*DN + tid] = (x2 - mean) * rsqrtf(var + 1e-5f) * g1[tid] + b1[tid];
}

// ---------------- k_srctgt : s = x@Ws+bs, t = x@Wt+bt ----------------
// grid = 512, 256 threads
__global__ void __launch_bounds__(256)
k_srctgt(const float* __restrict__ Wsm, const float* __restrict__ bsv,
         const float* __restrict__ Wtm, const float* __restrict__ btv) {
    __shared__ float xs[DN];
    int row = blockIdx.x, tid = threadIdx.x;
    if (tid < DN) xs[tid] = g_x[row*DN + tid];
    __syncthreads();
    float s = bsv[tid], t = btv[tid];
#pragma unroll 4
    for (int k = 0; k < DN; k++) {
        float xv = xs[k];
        s += xv * Wsm[k*DEH + tid];
        t += xv * Wtm[k*DEH + tid];
    }
    g_s[row*DEH + tid] = s;
    g_t[row*DEH + tid] = t;
}

// ---------------- k_e1 : h = gelu(ecat@We0+be0+src+tgt); e' = LN(e + h@We1+be1) ----------------
// grid = 512 (b,i), 256 threads, dynamic smem
#define E1_SMEM_F (32768 + 16384 + 256 + 512 + 1024 + 16)
__global__ void __launch_bounds__(256, 1)
k_e1(const float* __restrict__ e_in, float* __restrict__ e_out,
     const float* __restrict__ We0, const float* __restrict__ be0,
     const float* __restrict__ We1, const float* __restrict__ be1,
     const float* __restrict__ g0, const float* __restrict__ b0) {
    extern __shared__ float sm[];
    float* W0s  = sm;             // 128 x 256
    float* W1s  = W0s + 32768;    // 256 x 64
    float* srcs = W1s + 16384;    // 256
    float* ecat = srcs + 256;     // 4 x 128
    float* hid  = ecat + 512;     // 4 x 256
    float* redS = hid + 1024;     // 8
    float* redQ = redS + 8;       // 8

    int bi = blockIdx.x;
    int b = bi >> 8, i = bi & 255;
    int tid = threadIdx.x;

    {
        const float4* Wg0 = (const float4*)We0;
        float4* d0 = (float4*)W0s;
        for (int idx = tid; idx < 8192; idx += 256) d0[idx] = Wg0[idx];
        const float4* Wg1 = (const float4*)We1;
        float4* d1 = (float4*)W1s;
        for (int idx = tid; idx < 4096; idx += 256) d1[idx] = Wg1[idx];
    }
    srcs[tid] = g_s[bi*DEH + tid] + be0[tid];
    __syncthreads();

    int jj2 = tid >> 6, c2 = tid & 63;   // phase2 mapping
    int wmy = tid >> 5;

    for (int j0 = 0; j0 < NN; j0 += 4) {
        // stage ecat = [e_ij, e_ji] for 4 pairs
#pragma unroll
        for (int it = 0; it < 2; it++) {
            int idx = tid + it*256;
            int jj = idx >> 7, c = idx & 127;
            int j = j0 + jj;
            float v;
            if (c < 64) v = e_in[((size_t)bi*NN + j)*DE + c];
            else        v = e_in[(((size_t)b*NN + j)*NN + i)*DE + (c - 64)];
            ecat[idx] = v;
        }
        __syncthreads();

        // phase1: hidden col c = tid for 4 pairs
        float a0 = srcs[tid] + g_t[((size_t)b*NN + (j0+0))*DEH + tid];
        float a1 = srcs[tid] + g_t[((size_t)b*NN + (j0+1))*DEH + tid];
        float a2 = srcs[tid] + g_t[((size_t)b*NN + (j0+2))*DEH + tid];
        float a3 = srcs[tid] + g_t[((size_t)b*NN + (j0+3))*DEH + tid];
#pragma unroll 8
        for (int k = 0; k < 128; k++) {
            float w = W0s[k*256 + tid];
            a0 += ecat[k]       * w;
            a1 += ecat[128 + k] * w;
            a2 += ecat[256 + k] * w;
            a3 += ecat[384 + k] * w;
        }
        hid[tid]       = gelu_f(a0);
        hid[256 + tid] = gelu_f(a1);
        hid[512 + tid] = gelu_f(a2);
        hid[768 + tid] = gelu_f(a3);
        __syncthreads();

        // phase2: out col c (64) for pair jj
        int j = j0 + jj2;
        float o = be1[c2];
        const float* hp = hid + jj2*256;
#pragma unroll 8
        for (int k = 0; k < 256; k++) o += hp[k] * W1s[k*64 + c2];
        float r = ecat[jj2*128 + c2] + o;

        float s1 = r, s2 = r*r;
        for (int off = 16; off; off >>= 1) {
            s1 += __shfl_xor_sync(0xffffffffu, s1, off);
            s2 += __shfl_xor_sync(0xffffffffu, s2, off);
        }
        if ((tid & 31) == 0) { redS[wmy] = s1; redQ[wmy] = s2; }
        __syncthreads();
        float sum = redS[2*jj2] + redS[2*jj2+1];
        float sq  = redQ[2*jj2] + redQ[2*jj2+1];
        float mean = sum * (1.0f/DE);
        float var  = sq  * (1.0f/DE) - mean*mean;
        e_out[((size_t)bi*NN + j)*DE + c2] =
            (r - mean) * rsqrtf(var + 1e-5f) * g0[c2] + b0[c2];
        __syncthreads();
    }
}

// ---------------- k_e2 : e = LN(e + gelu(e@Wem1)@Wem2 + bem2) in place ----------------
// grid = 512, 256 threads, dynamic smem
#define E2_SMEM_F (16384 + 16384 + 256 + 1024 + 16)
__global__ void __launch_bounds__(256, 1)
k_e2(float* __restrict__ e_io,
     const float* __restrict__ Wem1, const float* __restrict__ Wem2,
     const float* __restrict__ bem2,
     const float* __restrict__ g1, const float* __restrict__ b1) {
    extern __shared__ float sm[];
    float* W1s = sm;            // 64 x 256
    float* W2s = W1s + 16384;   // 256 x 64
    float* es  = W2s + 16384;   // 4 x 64
    float* hid = es + 256;      // 4 x 256
    float* redS = hid + 1024;   // 8
    float* redQ = redS + 8;     // 8

    int bi = blockIdx.x, tid = threadIdx.x;
    {
        const float4* Wg1 = (const float4*)Wem1;
        float4* d1 = (float4*)W1s;
        for (int idx = tid; idx < 4096; idx += 256) d1[idx] = Wg1[idx];
        const float4* Wg2 = (const float4*)Wem2;
        float4* d2 = (float4*)W2s;
        for (int idx = tid; idx < 4096; idx += 256) d2[idx] = Wg2[idx];
    }
    __syncthreads();

    int jj2 = tid >> 6, c2 = tid & 63;
    int wmy = tid >> 5;

    for (int j0 = 0; j0 < NN; j0 += 4) {
        es[tid] = e_io[((size_t)bi*NN + (j0 + jj2))*DE + c2];
        __syncthreads();

        float a0 = 0.f, a1 = 0.f, a2 = 0.f, a3 = 0.f;
#pragma unroll 8
        for (int k = 0; k < 64; k++) {
            float w = W1s[k*256 + tid];
            a0 += es[k]       * w;
            a1 += es[64 + k]  * w;
            a2 += es[128 + k] * w;
            a3 += es[192 + k] * w;
        }
        hid[tid]       = gelu_f(a0);
        hid[256 + tid] = gelu_f(a1);
        hid[512 + tid] = gelu_f(a2);
        hid[768 + tid] = gelu_f(a3);
        __syncthreads();

        float o = bem2[c2];
        const float* hp = hid + jj2*256;
#pragma unroll 8
        for (int k = 0; k < 256; k++) o += hp[k] * W2s[k*64 + c2];
        float r = es[tid] + o;

        float s1 = r, s2 = r*r;
        for (int off = 16; off; off >>= 1) {
            s1 += __shfl_xor_sync(0xffffffffu, s1, off);
            s2 += __shfl_xor_sync(0xffffffffu, s2, off);
        }
        if ((tid & 31) == 0) { redS[wmy] = s1; redQ[wmy] = s2; }
        __syncthreads();
        float sum = redS[2*jj2] + redS[2*jj2+1];
        float sq  = redQ[2*jj2] + redQ[2*jj2+1];
        float mean = sum * (1.0f/DE);
        float var  = sq  * (1.0f/DE) - mean*mean;
        e_io[((size_t)bi*NN + (j0 + jj2))*DE + c2] =
            (r - mean) * rsqrtf(var + 1e-5f) * g1[c2] + b1[c2];
        __syncthreads();
    }
}

// ---------------- k_final : pack (x, e) into d_out ----------------
__global__ void k_final(float* __restrict__ out) {
    int idx = blockIdx.x * blockDim.x + threadIdx.x;
    const int nx = BB*NN*DN;
    const int ne = BB*NN*NN*DE;
    if (idx < nx) out[idx] = g_x[idx];
    else if (idx < nx + ne) out[idx] = g_ebuf0[idx - nx];
}

// ---------------- launch ----------------
extern "C" void kernel_launch(void* const* d_in, const int* in_sizes, int n_in,
                              void* d_out, int out_size) {
    const float* node    = (const float*)d_in[0];
    const float* edge    = (const float*)d_in[1];
    const float* Wqkv_n  = (const float*)d_in[2];
    const float* Wqkv_e  = (const float*)d_in[3];
    const float* Wo      = (const float*)d_in[4];
    const float* bo      = (const float*)d_in[5];
    const float* Wl0     = (const float*)d_in[6];
    const float* bl0     = (const float*)d_in[7];
    const float* ln0_g   = (const float*)d_in[8];
    const float* ln0_b   = (const float*)d_in[9];
    const float* Wm1     = (const float*)d_in[10];
    const float* Wm2     = (const float*)d_in[11];
    const float* bm2     = (const float*)d_in[12];
    const float* ln1_g   = (const float*)d_in[13];
    const float* ln1_b   = (const float*)d_in[14];
    const float* We0     = (const float*)d_in[15];
    const float* be0     = (const float*)d_in[16];
    const float* Wsm     = (const float*)d_in[17];
    const float* bsv     = (const float*)d_in[18];
    const float* Wtm     = (const float*)d_in[19];
    const float* btv     = (const float*)d_in[20];
    const float* We1     = (const float*)d_in[21];
    const float* be1     = (const float*)d_in[22];
    const float* eln0_g  = (const float*)d_in[23];
    const float* eln0_b  = (const float*)d_in[24];
    const float* Wem1    = (const float*)d_in[25];
    const float* Wem2    = (const float*)d_in[26];
    const float* bem2    = (const float*)d_in[27];
    const float* eln1_g  = (const float*)d_in[28];
    const float* eln1_b  = (const float*)d_in[29];
    float* out = (float*)d_out;

    cudaFuncSetAttribute(k_attn1, cudaFuncAttributeMaxDynamicSharedMemorySize, ATTN1_SMEM_F*4);
    cudaFuncSetAttribute(k_e1,    cudaFuncAttributeMaxDynamicSharedMemorySize, E1_SMEM_F*4);
    cudaFuncSetAttribute(k_e2,    cudaFuncAttributeMaxDynamicSharedMemorySize, E2_SMEM_F*4);

    float *pe0, *pe1;
    cudaGetSymbolAddress((void**)&pe0, g_ebuf0);
    cudaGetSymbolAddress((void**)&pe1, g_ebuf1);

    k_copy_x<<<(BB*NN*DN + 255)/256, 256>>>(node);

    const float* e_in = edge;   // layer 0 reads original edge features
    float* e_out = pe1;

    for (int l = 0; l < LL; l++) {
        k_qkvn<<<BB*NN, 128>>>(Wqkv_n + (size_t)l*DN*3*DH);
        k_attn1<<<BB*NN, 256, ATTN1_SMEM_F*4>>>(e_in, Wqkv_e + (size_t)l*DE*4*DH);
        k_attn2<<<BB*NN, 128>>>(Wo + (size_t)l*DH*DN, bo + (size_t)l*DN,
                                Wl0 + (size_t)l*DN*DN, bl0 + (size_t)l*DN,
                                ln0_g + (size_t)l*DN, ln0_b + (size_t)l*DN,
                                Wm1 + (size_t)l*DN*DNH, Wm2 + (size_t)l*DNH*DN,
                                bm2 + (size_t)l*DN,
                                ln1_g + (size_t)l*DN, ln1_b + (size_t)l*DN);
        k_srctgt<<<BB*NN, 256>>>(Wsm + (size_t)l*DN*DEH, bsv + (size_t)l*DEH,
                                 Wtm + (size_t)l*DN*DEH, btv + (size_t)l*DEH);
        k_e1<<<BB*NN, 256, E1_SMEM_F*4>>>(e_in, e_out,
                                          We0 + (size_t)l*2*DE*DEH, be0 + (size_t)l*DEH,
                                          We1 + (size_t)l*DEH*DE, be1 + (size_t)l*DE,
                                          eln0_g + (size_t)l*DE, eln0_b + (size_t)l*DE);
        k_e2<<<BB*NN, 256, E2_SMEM_F*4>>>(e_out,
                                          Wem1 + (size_t)l*DE*DEH, Wem2 + (size_t)l*DEH*DE,
                                          bem2 + (size_t)l*DE,
                                          eln1_g + (size_t)l*DE, eln1_b + (size_t)l*DE);
        e_in = e_out;
        e_out = pe0;   // layer 1 writes the final buffer
    }

    int total = BB*NN*DN + BB*NN*NN*DE;
    k_final<<<(total + 255)/256, 256>>>(out);
}

// round 12
// speedup vs baseline: 1.6638x; 1.6622x over previous
#include <cuda_runtime.h>
#include <cuda_bf16.h>
#include <cstdint>
#include <cstddef>

// ---------------- dims ----------------
#define BB   2
#define NN   256
#define DN   128
#define DE   64
#define DH   128
#define HH   8
#define DHH  16
#define DNH  512
#define DEH  256
#define LL   2

#define SCALE 0.08838834764831845f   // 1/sqrt(128)

typedef unsigned long long ull;

// ---------------- packed f32x2 helpers ----------------
__device__ __forceinline__ ull fma2(ull a, ull b, ull c) {
    ull d;
    asm("fma.rn.f32x2 %0, %1, %2, %3;" : "=l"(d) : "l"(a), "l"(b), "l"(c));
    return d;
}
__device__ __forceinline__ ull dup2f(float x) {
    ull r; asm("mov.b64 %0, {%1, %1};" : "=l"(r) : "f"(x)); return r;
}
__device__ __forceinline__ float2 unpk(ull v) {
    float2 r; asm("mov.b64 {%0, %1}, %2;" : "=f"(r.x), "=f"(r.y) : "l"(v)); return r;
}

__device__ __forceinline__ float gelu_f(float x) {
    return 0.5f * x * (1.0f + erff(x * 0.70710678118654752440f));
}

// ---------------- persistent scratch ----------------
__device__ float g_x[BB*NN*DN];
__device__ float g_qkvn[BB*NN*3*DH];
__device__ float g_ao[BB*NN*DH];                 // fused attention output
__device__ float g_s[BB*NN*DEH];
__device__ float g_t[BB*NN*DEH];
__device__ float g_ebuf1[(size_t)BB*NN*NN*DE];
__device__ float g_ebuf0[(size_t)BB*NN*NN*DE];

// ---------------- k_copy_x ----------------
__global__ void k_copy_x(const float* __restrict__ node) {
    int i = blockIdx.x * blockDim.x + threadIdx.x;
    if (i < BB*NN*DN) g_x[i] = node[i];
}

// ---------------- k_qkvn ----------------
__global__ void k_qkvn(const float* __restrict__ W) {
    __shared__ float xs[DN];
    int row = blockIdx.x, tid = threadIdx.x;
    xs[tid] = g_x[row*DN + tid];
    __syncthreads();
    float a0 = 0.f, a1 = 0.f, a2 = 0.f;
#pragma unroll 8
    for (int k = 0; k < DN; k++) {
        float xv = xs[k];
        const float* w = W + k*384;
        a0 += xv * w[tid];
        a1 += xv * w[tid + 128];
        a2 += xv * w[tid + 256];
    }
    float* o = g_qkvn + row*384;
    o[tid] = a0; o[tid + 128] = a1; o[tid + 256] = a2;
}

// ================= k_attn1 : fused edge-qkv GEMM + dots + v + softmax + AV =================
// grid 512 (b*N+i), 256 threads.
// smem (floats):
//  Ws    [0,32768)            Wqkv_e 64x512
//  ed    [32768,33792)        ull[64][8]   duplicated e row slice
//  qkvs  [33792,37888)        ull[8][256]  GEMM out for 8 j
//  dots  [37888,39936)        [8][256]
//  vsm   [39936,56320)        bf16[256][128]
//  qns   [56320,56448)
//  invs  [56448,56456)
//  pav   [56456,56712)
#define A1_SMEM_F 56712
__global__ void __launch_bounds__(256, 1)
k_attn1(const float* __restrict__ e_in, const float* __restrict__ W) {
    extern __shared__ float sm[];
    float* Ws   = sm;
    ull*   Ws2  = (ull*)Ws;
    ull*   ed   = (ull*)(sm + 32768);
    float* qkvs = sm + 33792;
    ull*   qkvs2 = (ull*)qkvs;
    float* dots = sm + 37888;
    __nv_bfloat16* vsm = (__nv_bfloat16*)(sm + 39936);
    float* qns  = sm + 56320;
    float* invs = sm + 56448;
    float* pav  = sm + 56456;

    int bi = blockIdx.x, b = bi >> 8, tid = threadIdx.x;

    {   // weights 32768 f
        const float4* Wg = (const float4*)W;
        float4* Wd = (float4*)Ws;
#pragma unroll
        for (int it = 0; it < 32; it++) Wd[tid + it*256] = Wg[tid + it*256];
    }
    if (tid < 128) qns[tid] = g_qkvn[bi*384 + (tid>>4)*48 + (tid&15)];

    int sj = tid >> 6, skk = tid & 63;   // staging map (2 vals/thread)
    float r0 = e_in[((size_t)bi*NN + sj)*DE + skk];
    float r1 = e_in[((size_t)bi*NN + 4 + sj)*DE + skk];
    __syncthreads();

    int hd = tid & 127, jgx = tid >> 7;
    int h = hd >> 4, d = hd & 15;

    for (int j0 = 0; j0 < NN; j0 += 8) {
        ed[skk*8 + sj]     = dup2f(r0);
        ed[skk*8 + 4 + sj] = dup2f(r1);
        __syncthreads();
        if (j0 + 8 < NN) {
            r0 = e_in[((size_t)bi*NN + (j0+8+sj))*DE + skk];
            r1 = e_in[((size_t)bi*NN + (j0+12+sj))*DE + skk];
        }
        // GEMM: thread = column pair (tid of 256), all 8 j
        ull a0=0,a1=0,a2=0,a3=0,a4=0,a5=0,a6=0,a7=0;
#pragma unroll
        for (int k = 0; k < 64; k++) {
            ull w = Ws2[k*256 + tid];
            ulonglong2 ea = *(const ulonglong2*)(ed + k*8);
            ulonglong2 eb = *(const ulonglong2*)(ed + k*8 + 2);
            ulonglong2 ec = *(const ulonglong2*)(ed + k*8 + 4);
            ulonglong2 eD = *(const ulonglong2*)(ed + k*8 + 6);
            a0 = fma2(ea.x, w, a0); a1 = fma2(ea.y, w, a1);
            a2 = fma2(eb.x, w, a2); a3 = fma2(eb.y, w, a3);
            a4 = fma2(ec.x, w, a4); a5 = fma2(eD.x, w, a5);
            a6 = fma2(ec.y, w, a6); a7 = fma2(eD.y, w, a7);
        }
        qkvs2[0*256 + tid] = a0; qkvs2[1*256 + tid] = a1;
        qkvs2[2*256 + tid] = a2; qkvs2[3*256 + tid] = a3;
        qkvs2[4*256 + tid] = a4; qkvs2[6*256 + tid] = a5;
        qkvs2[5*256 + tid] = a6; qkvs2[7*256 + tid] = a7;
        __syncthreads();

        // epilogue: (h,d) x 4 j per thread
        float qn = qns[hd];
#pragma unroll
        for (int jj = 0; jj < 4; jj++) {
            int jr = jgx*4 + jj, j = j0 + jr;
            const float* qv = qkvs + jr*512 + h*64 + d;
            float eq = qv[0], ek = qv[16], ev = qv[32], em = qv[48];
            const float* kv = g_qkvn + (size_t)(b*NN + j)*384 + h*48 + d;
            float kn = kv[16], vn = kv[32];
            float pd = (qn + eq) * (kn + ek);
            pd += __shfl_xor_sync(0xffffffffu, pd, 8);
            pd += __shfl_xor_sync(0xffffffffu, pd, 4);
            pd += __shfl_xor_sync(0xffffffffu, pd, 2);
            pd += __shfl_xor_sync(0xffffffffu, pd, 1);
            if (d == 0) dots[h*256 + j] = pd * SCALE;
            vsm[j*128 + hd] = __float2bfloat16(vn*em + ev);
        }
        __syncthreads();
    }

    // softmax: warp w = head w
    {
        int wid = tid >> 5, lane = tid & 31;
        float* dr = dots + wid*256;
        float vr[8]; float m = -1e30f;
#pragma unroll
        for (int q = 0; q < 8; q++) { vr[q] = dr[q*32 + lane]; m = fmaxf(m, vr[q]); }
#pragma unroll
        for (int o = 16; o; o >>= 1) m = fmaxf(m, __shfl_xor_sync(0xffffffffu, m, o));
        float s = 0.f;
#pragma unroll
        for (int q = 0; q < 8; q++) { float p = __expf(vr[q] - m); dr[q*32 + lane] = p; s += p; }
#pragma unroll
        for (int o = 16; o; o >>= 1) s += __shfl_xor_sync(0xffffffffu, s, o);
        if (lane == 0) invs[wid] = 1.f/s;
    }
    __syncthreads();

    // AV: thread (hd, half), sum over 128 j
    {
        int half = tid >> 7;
        const float* pr = dots + h*256 + half*128;
        const __nv_bfloat16* vp = vsm + (size_t)half*128*128 + hd;
        float acc = 0.f;
#pragma unroll 8
        for (int jj = 0; jj < 128; jj++)
            acc += pr[jj] * __bfloat162float(vp[jj*128]);
        pav[half*128 + hd] = acc;
    }
    __syncthreads();
    if (tid < 128)
        g_ao[bi*128 + tid] = (pav[tid] + pav[128 + tid]) * invs[tid>>4];
}

// ---------------- k_attn2 : Wo + Wl0 + LN + node MLP + LN ----------------
__global__ void __launch_bounds__(128)
k_attn2(const float* __restrict__ Wo, const float* __restrict__ bo,
        const float* __restrict__ Wl0, const float* __restrict__ bl0,
        const float* __restrict__ g0, const float* __restrict__ b0,
        const float* __restrict__ Wm1, const float* __restrict__ Wm2,
        const float* __restrict__ bm2,
        const float* __restrict__ g1, const float* __restrict__ b1) {
    __shared__ float outs[DH];
    __shared__ float hid[DNH];
    __shared__ float red[8];
    __shared__ float asm_[DH];
    __shared__ float xs[DN];

    int bi = blockIdx.x, tid = threadIdx.x;
    outs[tid] = g_ao[bi*128 + tid];
    __syncthreads();

    float ao = bo[tid];
#pragma unroll 4
    for (int k = 0; k < DH; k++) ao += outs[k] * Wo[k*DN + tid];
    asm_[tid] = ao;
    __syncthreads();

    float y = bl0[tid];
#pragma unroll 4
    for (int k = 0; k < DN; k++) y += asm_[k] * Wl0[k*DN + tid];
    float xv = g_x[bi*DN + tid] + y;

    float s1 = xv, s2 = xv*xv;
    for (int o = 16; o; o >>= 1) { s1 += __shfl_xor_sync(0xffffffffu, s1, o); s2 += __shfl_xor_sync(0xffffffffu, s2, o); }
    int w = tid >> 5;
    if ((tid & 31) == 0) { red[w*2] = s1; red[w*2+1] = s2; }
    __syncthreads();
    s1 = red[0]+red[2]+red[4]+red[6];
    s2 = red[1]+red[3]+red[5]+red[7];
    float mean = s1 * (1.0f/DN);
    float var  = s2 * (1.0f/DN) - mean*mean;
    float x1 = (xv - mean) * rsqrtf(var + 1e-5f) * g0[tid] + b0[tid];
    xs[tid] = x1;
    __syncthreads();

    {
        float4 hv = {0.f,0.f,0.f,0.f};
        const float4* W1 = (const float4*)Wm1;
#pragma unroll 4
        for (int k = 0; k < DN; k++) {
            float xk = xs[k];
            float4 wv = W1[k*(DNH/4) + tid];
            hv.x += xk*wv.x; hv.y += xk*wv.y; hv.z += xk*wv.z; hv.w += xk*wv.w;
        }
        hid[4*tid+0] = gelu_f(hv.x);
        hid[4*tid+1] = gelu_f(hv.y);
        hid[4*tid+2] = gelu_f(hv.z);
        hid[4*tid+3] = gelu_f(hv.w);
    }
    __syncthreads();

    float o2 = bm2[tid];
#pragma unroll 4
    for (int k = 0; k < DNH; k++) o2 += hid[k] * Wm2[k*DN + tid];
    float x2 = x1 + o2;

    s1 = x2; s2 = x2*x2;
    for (int o = 16; o; o >>= 1) { s1 += __shfl_xor_sync(0xffffffffu, s1, o); s2 += __shfl_xor_sync(0xffffffffu, s2, o); }
    __syncthreads();
    if ((tid & 31) == 0) { red[w*2] = s1; red[w*2+1] = s2; }
    __syncthreads();
    s1 = red[0]+red[2]+red[4]+red[6];
    s2 = red[1]+red[3]+red[5]+red[7];
    mean = s1 * (1.0f/DN);
    var  = s2 * (1.0f/DN) - mean*mean;
    g_x[bi*DN + tid] = (x2 - mean) * rsqrtf(var + 1e-5f) * g1[tid] + b1[tid];
}

// ---------------- k_srctgt ----------------
__global__ void __launch_bounds__(256)
k_srctgt(const float* __restrict__ Wsm, const float* __restrict__ bsv,
         const float* __restrict__ Wtm, const float* __restrict__ btv) {
    __shared__ float xs[DN];
    int row = blockIdx.x, tid = threadIdx.x;
    if (tid < DN) xs[tid] = g_x[row*DN + tid];
    __syncthreads();
    float s = bsv[tid], t = btv[tid];
#pragma unroll 4
    for (int k = 0; k < DN; k++) {
        float xv = xs[k];
        s += xv * Wsm[k*DEH + tid];
        t += xv * Wtm[k*DEH + tid];
    }
    g_s[row*DEH + tid] = s;
    g_t[row*DEH + tid] = t;
}

// ================= k_e1 : fused edge MLP1 + residual + LN =================
// grid 512, 256 threads.
// smem (floats):
//  W0s   [0,32768)        We0 128x256
//  W1s   [32768,49152)    We1 256x64
//  ecatd [49152,51200)    ull[128][8]
//  hiddp [51200,55552)    ull[128][17]
//  psum  [55552,57600)    ull[4][8][32]
//  srcs  [57600,57856)
#define E1_SMEM_F 57856
__global__ void __launch_bounds__(256, 1)
k_e1(const float* __restrict__ e_in, float* __restrict__ e_out,
     const float* __restrict__ We0, const float* __restrict__ be0,
     const float* __restrict__ We1, const float* __restrict__ be1,
     const float* __restrict__ g0, const float* __restrict__ b0) {
    extern __shared__ float sm[];
    float* W0s = sm;          ull* W0s2 = (ull*)W0s;
    float* W1s = sm + 32768;  ull* W1s2 = (ull*)W1s;
    ull* ecatd = (ull*)(sm + 49152);
    ull* hiddp = (ull*)(sm + 51200);
    ull* psum  = (ull*)(sm + 55552);
    float* srcs = sm + 57600;

    int bi = blockIdx.x, b = bi >> 8, i = bi & 255, tid = threadIdx.x;

    {
        const float4* w0 = (const float4*)We0; float4* d0 = (float4*)W0s;
#pragma unroll
        for (int it = 0; it < 32; it++) d0[tid + it*256] = w0[tid + it*256];
        const float4* w1 = (const float4*)We1; float4* d1 = (float4*)W1s;
#pragma unroll
        for (int it = 0; it < 16; it++) d1[tid + it*256] = w1[tid + it*256];
    }
    srcs[tid] = g_s[bi*DEH + tid] + be0[tid];

    // staging map: 1024 vals = 4/thread
    float rv[4];
#pragma unroll
    for (int it = 0; it < 4; it++) {
        int idx = tid + it*256, j = idx >> 7, kk = idx & 127;
        rv[it] = (kk < 64) ? e_in[((size_t)bi*NN + j)*DE + kk]
                           : e_in[(((size_t)b*NN + j)*NN + i)*DE + (kk - 64)];
    }
    __syncthreads();

    int cp1 = tid & 127, jgx = tid >> 7;                 // phase1
    int c2p = tid & 31, jgx2 = (tid >> 5) & 1, ks = tid >> 6;  // phase2
    int jc = tid >> 5, cpc = tid & 31;                   // combine

    for (int j0 = 0; j0 < NN; j0 += 8) {
#pragma unroll
        for (int it = 0; it < 4; it++) {
            int idx = tid + it*256, j = idx >> 7, kk = idx & 127;
            ecatd[kk*8 + j] = dup2f(rv[it]);
        }
        __syncthreads();
        if (j0 + 8 < NN) {
#pragma unroll
            for (int it = 0; it < 4; it++) {
                int idx = tid + it*256, j = (idx >> 7) + j0 + 8, kk = idx & 127;
                rv[it] = (kk < 64) ? e_in[((size_t)bi*NN + j)*DE + kk]
                                   : e_in[(((size_t)b*NN + j)*NN + i)*DE + (kk - 64)];
            }
        }
        // phase1: thread = hid col pair cp1, 4 j
        ull acc[4];
        {
            float2 sv = ((const float2*)srcs)[cp1];
#pragma unroll
            for (int jj = 0; jj < 4; jj++) {
                int j = j0 + jgx*4 + jj;
                float2 tv = ((const float2*)(g_t + (size_t)(b*NN + j)*DEH))[cp1];
                float2 in2 = { sv.x + tv.x, sv.y + tv.y };
                acc[jj] = *(const ull*)&in2;
            }
        }
#pragma unroll
        for (int k = 0; k < 128; k++) {
            ull w = W0s2[k*128 + cp1];
            ulonglong2 ea = *(const ulonglong2*)(ecatd + k*8 + jgx*4);
            ulonglong2 eb = *(const ulonglong2*)(ecatd + k*8 + jgx*4 + 2);
            acc[0] = fma2(ea.x, w, acc[0]);
            acc[1] = fma2(ea.y, w, acc[1]);
            acc[2] = fma2(eb.x, w, acc[2]);
            acc[3] = fma2(eb.y, w, acc[3]);
        }
#pragma unroll
        for (int jj = 0; jj < 4; jj++) {
            float2 f = unpk(acc[jj]);
            int j = jgx*4 + jj;
            hiddp[cp1*17 + j*2 + 0] = dup2f(gelu_f(f.x));
            hiddp[cp1*17 + j*2 + 1] = dup2f(gelu_f(f.y));
        }
        __syncthreads();

        // phase2: out col pair c2p, 4 j, k-split 4
        {
            ull p0=0, p1=0, p2=0, p3=0;
            int kb = ks*64;
#pragma unroll
            for (int kk = 0; kk < 64; kk++) {
                int k = kb + kk;
                ull w = W1s2[k*32 + c2p];
                const ull* hp = hiddp + (k>>1)*17 + (k&1) + jgx2*8;
                p0 = fma2(hp[0], w, p0);
                p1 = fma2(hp[2], w, p1);
                p2 = fma2(hp[4], w, p2);
                p3 = fma2(hp[6], w, p3);
            }
            int jb = jgx2*4;
            psum[(ks*8 + jb+0)*32 + c2p] = p0;
            psum[(ks*8 + jb+1)*32 + c2p] = p1;
            psum[(ks*8 + jb+2)*32 + c2p] = p2;
            psum[(ks*8 + jb+3)*32 + c2p] = p3;
        }
        __syncthreads();

        // combine + residual + LN: warp = one j (32 col pairs)
        {
            float2 q0 = unpk(psum[(0*8 + jc)*32 + cpc]);
            float2 q1 = unpk(psum[(1*8 + jc)*32 + cpc]);
            float2 q2 = unpk(psum[(2*8 + jc)*32 + cpc]);
            float2 q3 = unpk(psum[(3*8 + jc)*32 + cpc]);
            float2 bia = ((const float2*)be1)[cpc];
            float2 res = ((const float2*)(e_in + ((size_t)bi*NN + j0 + jc)*DE))[cpc];
            float r0 = q0.x + q1.x + q2.x + q3.x + bia.x + res.x;
            float r1 = q0.y + q1.y + q2.y + q3.y + bia.y + res.y;
            float s1 = r0 + r1, s2 = r0*r0 + r1*r1;
#pragma unroll
            for (int o = 16; o; o >>= 1) {
                s1 += __shfl_xor_sync(0xffffffffu, s1, o);
                s2 += __shfl_xor_sync(0xffffffffu, s2, o);
            }
            float mean = s1 * (1.f/DE);
            float var  = s2 * (1.f/DE) - mean*mean;
            float rs = rsqrtf(var + 1e-5f);
            float2 gg = ((const float2*)g0)[cpc];
            float2 bb = ((const float2*)b0)[cpc];
            float2 o2 = { (r0 - mean)*rs*gg.x + bb.x, (r1 - mean)*rs*gg.y + bb.y };
            ((float2*)(e_out + ((size_t)bi*NN + j0 + jc)*DE))[cpc] = o2;
        }
        __syncthreads();
    }
}

// ================= k_e2 : fused edge MLP2 + residual + LN (in place) =================
// smem (floats):
//  W1s   [0,16384)       Wem1 64x256
//  W2s   [16384,32768)   Wem2 256x64
//  ed    [32768,33792)   ull[64][8]
//  hiddp [33792,38144)   ull[128][17]
//  psum  [38144,40192)   ull[4][8][32]
#define E2_SMEM_F 40192
__global__ void __launch_bounds__(256, 1)
k_e2(float* __restrict__ e_io,
     const float* __restrict__ Wem1, const float* __restrict__ Wem2,
     const float* __restrict__ bem2,
     const float* __restrict__ g1, const float* __restrict__ b1) {
    extern __shared__ float sm[];
    float* W1s = sm;          ull* W1s2 = (ull*)W1s;
    float* W2s = sm + 16384;  ull* W2s2 = (ull*)W2s;
    ull* ed    = (ull*)(sm + 32768);
    ull* hiddp = (ull*)(sm + 33792);
    ull* psum  = (ull*)(sm + 38144);

    int bi = blockIdx.x, tid = threadIdx.x;
    {
        const float4* w1 = (const float4*)Wem1; float4* d1 = (float4*)W1s;
#pragma unroll
        for (int it = 0; it < 16; it++) d1[tid + it*256] = w1[tid + it*256];
        const float4* w2 = (const float4*)Wem2; float4* d2 = (float4*)W2s;
#pragma unroll
        for (int it = 0; it < 16; it++) d2[tid + it*256] = w2[tid + it*256];
    }
    int sj = tid >> 6, skk = tid & 63;
    float r0 = e_io[((size_t)bi*NN + sj)*DE + skk];
    float r1 = e_io[((size_t)bi*NN + 4 + sj)*DE + skk];
    __syncthreads();

    int cp1 = tid & 127, jgx = tid >> 7;
    int c2p = tid & 31, jgx2 = (tid >> 5) & 1, ks = tid >> 6;
    int jc = tid >> 5, cpc = tid & 31;

    for (int j0 = 0; j0 < NN; j0 += 8) {
        ed[skk*8 + sj]     = dup2f(r0);
        ed[skk*8 + 4 + sj] = dup2f(r1);
        __syncthreads();
        if (j0 + 8 < NN) {
            r0 = e_io[((size_t)bi*NN + (j0+8+sj))*DE + skk];
            r1 = e_io[((size_t)bi*NN + (j0+12+sj))*DE + skk];
        }
        // phase1: k=64
        {
            ull acc[4] = {0ull, 0ull, 0ull, 0ull};
#pragma unroll
            for (int k = 0; k < 64; k++) {
                ull w = W1s2[k*128 + cp1];
                ulonglong2 ea = *(const ulonglong2*)(ed + k*8 + jgx*4);
                ulonglong2 eb = *(const ulonglong2*)(ed + k*8 + jgx*4 + 2);
                acc[0] = fma2(ea.x, w, acc[0]);
                acc[1] = fma2(ea.y, w, acc[1]);
                acc[2] = fma2(eb.x, w, acc[2]);
                acc[3] = fma2(eb.y, w, acc[3]);
            }
#pragma unroll
            for (int jj = 0; jj < 4; jj++) {
                float2 f = unpk(acc[jj]);
                int j = jgx*4 + jj;
                hiddp[cp1*17 + j*2 + 0] = dup2f(gelu_f(f.x));
                hiddp[cp1*17 + j*2 + 1] = dup2f(gelu_f(f.y));
            }
        }
        __syncthreads();

        // phase2: k=256, 4-way k split
        {
            ull p0=0, p1=0, p2=0, p3=0;
            int kb = ks*64;
#pragma unroll
            for (int kk = 0; kk < 64; kk++) {
                int k = kb + kk;
                ull w = W2s2[k*32 + c2p];
                const ull* hp = hiddp + (k>>1)*17 + (k&1) + jgx2*8;
                p0 = fma2(hp[0], w, p0);
                p1 = fma2(hp[2], w, p1);
                p2 = fma2(hp[4], w, p2);
                p3 = fma2(hp[6], w, p3);
            }
            int jb = jgx2*4;
            psum[(ks*8 + jb+0)*32 + c2p] = p0;
            psum[(ks*8 + jb+1)*32 + c2p] = p1;
            psum[(ks*8 + jb+2)*32 + c2p] = p2;
            psum[(ks*8 + jb+3)*32 + c2p] = p3;
        }
        __syncthreads();

        // combine + residual + LN
        {
            float2 q0 = unpk(psum[(0*8 + jc)*32 + cpc]);
            float2 q1 = unpk(psum[(1*8 + jc)*32 + cpc]);
            float2 q2 = unpk(psum[(2*8 + jc)*32 + cpc]);
            float2 q3 = unpk(psum[(3*8 + jc)*32 + cpc]);
            float2 bia = ((const float2*)bem2)[cpc];
            float2 res = ((const float2*)(e_io + ((size_t)bi*NN + j0 + jc)*DE))[cpc];
            float r0c = q0.x + q1.x + q2.x + q3.x + bia.x + res.x;
            float r1c = q0.y + q1.y + q2.y + q3.y + bia.y + res.y;
            float s1 = r0c + r1c, s2 = r0c*r0c + r1c*r1c;
#pragma unroll
            for (int o = 16; o; o >>= 1) {
                s1 += __shfl_xor_sync(0xffffffffu, s1, o);
                s2 += __shfl_xor_sync(0xffffffffu, s2, o);
            }
            float mean = s1 * (1.f/DE);
            float var  = s2 * (1.f/DE) - mean*mean;
            float rs = rsqrtf(var + 1e-5f);
            float2 gg = ((const float2*)g1)[cpc];
            float2 bb = ((const float2*)b1)[cpc];
            float2 o2 = { (r0c - mean)*rs*gg.x + bb.x, (r1c - mean)*rs*gg.y + bb.y };
            ((float2*)(e_io + ((size_t)bi*NN + j0 + jc)*DE))[cpc] = o2;
        }
        __syncthreads();
    }
}

// ---------------- k_final ----------------
__global__ void k_final(float* __restrict__ out) {
    int idx = blockIdx.x * blockDim.x + threadIdx.x;
    const int nx = BB*NN*DN;
    const int ne = BB*NN*NN*DE;
    if (idx < nx) out[idx] = g_x[idx];
    else if (idx < nx + ne) out[idx] = g_ebuf0[idx - nx];
}

// ---------------- launch ----------------
extern "C" void kernel_launch(void* const* d_in, const int* in_sizes, int n_in,
                              void* d_out, int out_size) {
    const float* node    = (const float*)d_in[0];
    const float* edge    = (const float*)d_in[1];
    const float* Wqkv_n  = (const float*)d_in[2];
    const float* Wqkv_e  = (const float*)d_in[3];
    const float* Wo      = (const float*)d_in[4];
    const float* bo      = (const float*)d_in[5];
    const float* Wl0     = (const float*)d_in[6];
    const float* bl0     = (const float*)d_in[7];
    const float* ln0_g   = (const float*)d_in[8];
    const float* ln0_b   = (const float*)d_in[9];
    const float* Wm1     = (const float*)d_in[10];
    const float* Wm2     = (const float*)d_in[11];
    const float* bm2     = (const float*)d_in[12];
    const float* ln1_g   = (const float*)d_in[13];
    const float* ln1_b   = (const float*)d_in[14];
    const float* We0     = (const float*)d_in[15];
    const float* be0     = (const float*)d_in[16];
    const float* Wsm     = (const float*)d_in[17];
    const float* bsv     = (const float*)d_in[18];
    const float* Wtm     = (const float*)d_in[19];
    const float* btv     = (const float*)d_in[20];
    const float* We1     = (const float*)d_in[21];
    const float* be1     = (const float*)d_in[22];
    const float* eln0_g  = (const float*)d_in[23];
    const float* eln0_b  = (const float*)d_in[24];
    const float* Wem1    = (const float*)d_in[25];
    const float* Wem2    = (const float*)d_in[26];
    const float* bem2    = (const float*)d_in[27];
    const float* eln1_g  = (const float*)d_in[28];
    const float* eln1_b  = (const float*)d_in[29];
    float* out = (float*)d_out;

    cudaFuncSetAttribute(k_attn1, cudaFuncAttributeMaxDynamicSharedMemorySize, A1_SMEM_F*4);
    cudaFuncSetAttribute(k_e1,    cudaFuncAttributeMaxDynamicSharedMemorySize, E1_SMEM_F*4);
    cudaFuncSetAttribute(k_e2,    cudaFuncAttributeMaxDynamicSharedMemorySize, E2_SMEM_F*4);

    float *pe0, *pe1;
    cudaGetSymbolAddress((void**)&pe0, g_ebuf0);
    cudaGetSymbolAddress((void**)&pe1, g_ebuf1);

    k_copy_x<<<(BB*NN*DN + 255)/256, 256>>>(node);

    const float* e_in = edge;
    float* e_out = pe1;

    for (int l = 0; l < LL; l++) {
        k_qkvn<<<BB*NN, 128>>>(Wqkv_n + (size_t)l*DN*3*DH);
        k_attn1<<<BB*NN, 256, A1_SMEM_F*4>>>(e_in, Wqkv_e + (size_t)l*DE*4*DH);
        k_attn2<<<BB*NN, 128>>>(Wo + (size_t)l*DH*DN, bo + (size_t)l*DN,
                                Wl0 + (size_t)l*DN*DN, bl0 + (size_t)l*DN,
                                ln0_g + (size_t)l*DN, ln0_b + (size_t)l*DN,
                                Wm1 + (size_t)l*DN*DNH, Wm2 + (size_t)l*DNH*DN,
                                bm2 + (size_t)l*DN,
                                ln1_g + (size_t)l*DN, ln1_b + (size_t)l*DN);
        k_srctgt<<<BB*NN, 256>>>(Wsm + (size_t)l*DN*DEH, bsv + (size_t)l*DEH,
                                 Wtm + (size_t)l*DN*DEH, btv + (size_t)l*DEH);
        k_e1<<<BB*NN, 256, E1_SMEM_F*4>>>(e_in, e_out,
                                          We0 + (size_t)l*2*DE*DEH, be0 + (size_t)l*DEH,
                                          We1 + (size_t)l*DEH*DE, be1 + (size_t)l*DE,
                                          eln0_g + (size_t)l*DE, eln0_b + (size_t)l*DE);
        k_e2<<<BB*NN, 256, E2_SMEM_F*4>>>(e_out,
                                          Wem1 + (size_t)l*DE*DEH, Wem2 + (size_t)l*DEH*DE,
                                          bem2 + (size_t)l*DE,
                                          eln1_g + (size_t)l*DE, eln1_b + (size_t)l*DE);
        e_in = e_out;
        e_out = pe0;
    }

    int total = BB*NN*DN + BB*NN*NN*DE;
    k_final<<<(total + 255)/256, 256>>>(out);
}